// round 12
// baseline (speedup 1.0000x reference)
#include <cuda_runtime.h>
#include <cstdint>

// Problem constants (from reference): B=8, N=65536, C=256, NPOINT=1024
#define BB        8
#define NN        65536
#define CC        256
#define NPOINTS   1024
#define CHUNKS    16                  // CTAs per batch == cluster size
#define TFPS      512                 // threads per FPS block
#define NWARP     (TFPS / 32)
#define PPB       (NN / CHUNKS)       // 4096 points per block
#define PPT       (PPB / TFPS)        // 8 points per thread

__device__ int g_inds[BB][NPOINTS];   // fully rewritten every run -> no init needed

struct InitFar { int v[BB]; };

// ---------------------------------------------------------------------------
// PTX helpers
// ---------------------------------------------------------------------------
__device__ __forceinline__ uint32_t smem_u32(const void* p) {
    uint32_t a;
    asm("{ .reg .u64 t; cvta.to.shared.u64 t, %1; cvt.u32.u64 %0, t; }" : "=r"(a) : "l"(p));
    return a;
}
__device__ __forceinline__ uint32_t my_ctarank() {
    uint32_t r; asm("mov.u32 %0, %%cluster_ctarank;" : "=r"(r)); return r;
}
__device__ __forceinline__ uint32_t mapa_u32(uint32_t local, uint32_t rank) {
    uint32_t r;
    asm("mapa.shared::cluster.u32 %0, %1, %2;" : "=r"(r) : "r"(local), "r"(rank));
    return r;
}
__device__ __forceinline__ void st_dsmem_u64(uint32_t addr, unsigned long long v) {
    asm volatile("st.relaxed.cluster.shared::cluster.u64 [%0], %1;" :: "r"(addr), "l"(v) : "memory");
}
// Volatile LDS/STS: 29-cyc fast path; aligned 8B smem accesses are atomic.
__device__ __forceinline__ unsigned long long ld_smem_vol_u64(uint32_t addr) {
    unsigned long long v;
    asm volatile("ld.volatile.shared.u64 %0, [%1];" : "=l"(v) : "r"(addr) : "memory");
    return v;
}
__device__ __forceinline__ void st_smem_vol_u64(uint32_t addr, unsigned long long v) {
    asm volatile("st.volatile.shared.u64 [%0], %1;" :: "r"(addr), "l"(v) : "memory");
}
__device__ __forceinline__ unsigned ld_smem_vol_u32(uint32_t addr) {
    unsigned v;
    asm volatile("ld.volatile.shared.u32 %0, [%1];" : "=r"(v) : "r"(addr) : "memory");
    return v;
}
__device__ __forceinline__ void st_smem_vol_u32(uint32_t addr, unsigned v) {
    asm volatile("st.volatile.shared.u32 [%0], %1;" :: "r"(addr), "r"(v) : "memory");
}
__device__ __forceinline__ unsigned redux_max_u32(unsigned v) {
    unsigned r;
    asm volatile("redux.sync.max.u32 %0, %1, 0xffffffff;" : "=r"(r) : "r"(v));
    return r;
}
__device__ __forceinline__ void cluster_sync_all() {
    asm volatile("barrier.cluster.arrive.aligned;" ::: "memory");
    asm volatile("barrier.cluster.wait.aligned;"   ::: "memory");
}

// Two-stage argmax on (dist, key) via redux.sync.max — identical ordering to
// a u64 (dist<<32|key) max: dist primary, then larger key (keys derive from
// ~idx, so larger key == smaller index == jnp.argmax first-occurrence).
__device__ __forceinline__ void redux_argmax(unsigned d, unsigned k,
                                             unsigned* md, unsigned* wk) {
    const unsigned m = redux_max_u32(d);
    const unsigned c = (d == m) ? k : 0u;
    *md = m;
    *wk = redux_max_u32(c);
}

// ---------------------------------------------------------------------------
// FPS: one batch = one 16-CTA cluster; BARRIER-FREE iteration body.
// All synchronization is tagged single-writer/single-reader mailboxes:
//   s_red[w]  (smem, u64): warp w's (dist,key), parity tag (it&1) in bit 31
//             of the low word. Warps run at most 1 iteration ahead (they need
//             s_far@it first), so parity disambiguates fresh vs stale.
//   cluster slots (DSMEM): unchanged proven protocol — double buffer (it&1)
//             + phase tag ((it>>1)&1), peers at most 1 iteration ahead.
//   s_far     (smem, u32): far | (it<<16); every warp spins until tag == it.
// Chain: compute -> warp redux -> STS s_red -> warp0 polls 16 slots ->
// redux -> DSMEM all-to-all -> poll own slots -> redux -> STS s_far ->
// warps resume. No __syncthreads, no atomics, no fences in the loop.
// ---------------------------------------------------------------------------
__global__ __launch_bounds__(TFPS, 1) __cluster_dims__(CHUNKS, 1, 1)
void fps_kernel(const float* __restrict__ xyz, InitFar init) {
    const int b    = blockIdx.y;
    const int t    = threadIdx.x;
    const int lane = t & 31;
    const int warp = t >> 5;
    const uint32_t rank = my_ctarank();          // == blockIdx.x
    const int base = (int)rank * PPB;

    __shared__ unsigned long long s_slots[2][CHUNKS];   // cluster mailbox
    __shared__ unsigned long long s_red[NWARP];         // intra-CTA warp mailbox
    __shared__ unsigned s_far;                          // tagged broadcast

    // Initialize tags to "invalid" for the first iterations
    if (t < 2 * CHUNKS) s_slots[t >> 4][t & 15] = 0x80000000ull;  // phase=1, iters 0/1 expect 0
    if (t < NWARP)      s_red[t] = 0x80000000ull;                 // parity=1, iter 0 expects 0
    if (t == 0)         s_far = 0xFFFF0000u;                      // tag 0xFFFF != it 0

    const float* __restrict__ xb = xyz + (size_t)b * NN * 3;

    float    px[PPT], py[PPT], pz[PPT], dist[PPT];
    unsigned ienc[PPT];
#pragma unroll
    for (int k = 0; k < PPT; ++k) {
        const int p = base + k * TFPS + t;
        const float* q = xb + 3 * (size_t)p;
        px[k] = q[0]; py[k] = q[1]; pz[k] = q[2];
        dist[k] = 1e10f;
        ienc[k] = ~(unsigned)p;
    }

    // Precomputed addresses
    const uint32_t a_red_mine = smem_u32(&s_red[warp]);            // producer store
    const uint32_t a_red_poll = smem_u32(&s_red[lane & (NWARP-1)]);// warp0 poll
    const uint32_t a_far      = smem_u32(&s_far);
    uint32_t st_addr[2], poll_addr[2];
    {
        const uint32_t l0 = smem_u32(&s_slots[0][rank]);
        const uint32_t l1 = smem_u32(&s_slots[1][rank]);
        const uint32_t peer = (lane < CHUNKS) ? (uint32_t)lane : 0u;
        st_addr[0] = mapa_u32(l0, peer);          // my value -> peer's slot[buf][rank]
        st_addr[1] = mapa_u32(l1, peer);
        poll_addr[0] = smem_u32(&s_slots[0][lane & 15]);  // my own slot[buf][lane]
        poll_addr[1] = smem_u32(&s_slots[1][lane & 15]);
    }

    __syncthreads();
    cluster_sync_all();   // all CTAs' slot tags initialized before any publish

    int far = init.v[b];

    for (int it = 0; it < NPOINTS; ++it) {
        const int buf = it & 1;
        const unsigned ptag  = (unsigned)(it & 1);         // intra-CTA parity tag
        const unsigned phase = (unsigned)((it >> 1) & 1);  // cluster phase tag

        if (rank == 0 && t == 0) g_inds[b][it] = far;      // lax.scan pre-update index

        // Centroid broadcast load (L2 hit; L1 after first warp)
        const float* cq = xb + 3 * (size_t)far;
        const float cx = __ldg(cq + 0);
        const float cy = __ldg(cq + 1);
        const float cz = __ldg(cq + 2);

        float    bd = -1.0f;
        unsigned bi = 0u;
#pragma unroll
        for (int k = 0; k < PPT; ++k) {
            // Match XLA (no FP contraction): sub, mul, (d0+d1)+d2, all RN
            const float dx = __fsub_rn(px[k], cx);
            const float dy = __fsub_rn(py[k], cy);
            const float dz = __fsub_rn(pz[k], cz);
            const float d  = __fadd_rn(__fadd_rn(__fmul_rn(dx, dx), __fmul_rn(dy, dy)),
                                       __fmul_rn(dz, dz));
            const float nd = fminf(dist[k], d);
            dist[k] = nd;
            if (nd > bd) { bd = nd; bi = ienc[k]; }        // strict > keeps smallest idx
        }

        // Warp argmax via 2x redux; publish tagged (d,k) to this warp's slot
        unsigned m0, w0;
        redux_argmax(__float_as_uint(bd), bi, &m0, &w0);

        if (warp != 0) {
            if (lane == 0) {
                const unsigned long long v =
                    ((unsigned long long)m0 << 32)
                    | (unsigned long long)((w0 & 0x7FFFFFFFu) | (ptag << 31));
                st_smem_vol_u64(a_red_mine, v);
            }
            // Spin until warp 0 broadcasts this iteration's winner
            unsigned fv;
            do { fv = ld_smem_vol_u32(a_far); } while ((fv >> 16) != (unsigned)it);
            far = (int)(fv & 0xFFFFu);
        } else {
            if (lane == 0) {
                const unsigned long long v =
                    ((unsigned long long)m0 << 32)
                    | (unsigned long long)((w0 & 0x7FFFFFFFu) | (ptag << 31));
                st_smem_vol_u64(a_red_mine, v);
            }

            // Poll the 16 warp slots (lane i watches s_red[i])
            unsigned long long v = 0ull;
            bool done = (lane >= NWARP);
            for (;;) {
                if (!done) {
                    v = ld_smem_vol_u64(a_red_poll);
                    done = (((unsigned)(v >> 31)) & 1u) == ptag;
                }
                if (__ballot_sync(0xFFFFFFFFu, done) == 0xFFFFFFFFu) break;
            }

            // Block argmax via 2x redux
            unsigned d2 = 0u, k2 = 0u;
            if (lane < NWARP) { d2 = (unsigned)(v >> 32); k2 = (unsigned)v; }
            unsigned m2, w2;
            redux_argmax(d2, k2, &m2, &w2);

            // Publish block winner to every CTA's slot[buf][rank]
            const unsigned long long blk =
                ((unsigned long long)m2 << 32)
                | (unsigned long long)((w2 & 0x7FFFFFFFu) | (phase << 31));
            if (lane < CHUNKS) st_dsmem_u64(st_addr[buf], blk);

            // Poll own cluster slots (lane r watches slot[buf][r])
            unsigned long long cv = 0ull;
            bool cdone = (lane >= CHUNKS);
            for (;;) {
                if (!cdone) {
                    cv = ld_smem_vol_u64(poll_addr[buf]);
                    cdone = (((unsigned)(cv >> 31)) & 1u) == phase;
                }
                if (__ballot_sync(0xFFFFFFFFu, cdone) == 0xFFFFFFFFu) break;
            }

            // Cluster argmax via 2x redux
            unsigned d3 = 0u, k3 = 0u;
            if (lane < CHUNKS) { d3 = (unsigned)(cv >> 32); k3 = (unsigned)cv; }
            unsigned m3, w3;
            redux_argmax(d3, k3, &m3, &w3);

            far = (int)((~w3) & 0xFFFFu);
            if (lane == 0)
                st_smem_vol_u32(a_far, (unsigned)far | ((unsigned)it << 16));
        }
    }

    cluster_sync_all();   // no CTA exits while peers might still address its SMEM
}

// ---------------------------------------------------------------------------
// Gather outputs. d_out (float32) layout, concatenated in reference order:
//   [0)                    new_xyz      (B, NPOINT, 3)
//   [B*NPOINT*3)           new_features (B, C, NPOINT)
//   [.. + B*C*NPOINT)      sample_inds  (B, NPOINT)  (indices as float)
// ---------------------------------------------------------------------------
__global__ void gather_kernel(const float* __restrict__ xyz,
                              const float* __restrict__ feat,
                              float* __restrict__ out) {
    const int b = blockIdx.x;
    const int c = blockIdx.y;

    float* out_xyz  = out;
    float* out_feat = out + (size_t)BB * NPOINTS * 3;
    float* out_inds = out_feat + (size_t)BB * CC * NPOINTS;

    const float* frow = feat + ((size_t)b * CC + c) * NN;
    float*       orow = out_feat + ((size_t)b * CC + c) * NPOINTS;

    for (int j = threadIdx.x; j < NPOINTS; j += blockDim.x) {
        const int idx = g_inds[b][j];
        orow[j] = __ldg(frow + idx);
        if (c == 0) {
            out_inds[(size_t)b * NPOINTS + j] = (float)idx;
            const float* q = xyz + ((size_t)b * NN + idx) * 3;
            float* o = out_xyz + ((size_t)b * NPOINTS + j) * 3;
            o[0] = __ldg(q + 0); o[1] = __ldg(q + 1); o[2] = __ldg(q + 2);
        }
    }
}

// ---------------------------------------------------------------------------
// Host: reproduce jax.random.randint(jax.random.key(1), (8,), 0, 65536)
// under jax_threefry_partitionable=True (default since JAX 0.5.0).
//   k1, k2 = split(key(1));  lower = random_bits(k2, 32, (8,));  idx = lower & 0xFFFF
//   split:       newkey_j = threefry2x32((0,1), (0, j))
//   random_bits: bits[b]  = o0 ^ o1 of threefry2x32(k2, (0, b))
// ---------------------------------------------------------------------------
static void threefry2x32_host(uint32_t k0, uint32_t k1, uint32_t c0, uint32_t c1,
                              uint32_t* o0, uint32_t* o1) {
    const uint32_t ks[3] = { k0, k1, k0 ^ k1 ^ 0x1BD11BDAu };
    static const int rot0[4] = {13, 15, 26, 6};
    static const int rot1[4] = {17, 29, 16, 24};
    uint32_t x0 = c0 + ks[0];
    uint32_t x1 = c1 + ks[1];
    for (int i = 0; i < 5; ++i) {
        const int* rr = (i % 2 == 0) ? rot0 : rot1;
        for (int j = 0; j < 4; ++j) {
            x0 += x1;
            x1 = (x1 << rr[j]) | (x1 >> (32 - rr[j]));
            x1 ^= x0;
        }
        x0 += ks[(i + 1) % 3];
        x1 += ks[(i + 2) % 3] + (uint32_t)(i + 1);
    }
    *o0 = x0; *o1 = x1;
}

extern "C" void kernel_launch(void* const* d_in, const int* in_sizes, int n_in,
                              void* d_out, int out_size) {
    (void)in_sizes; (void)n_in; (void)out_size;
    const float* xyz  = (const float*)d_in[0];
    const float* feat = (const float*)d_in[1];

    uint32_t k2a, k2b;
    threefry2x32_host(0u, 1u, 0u, 1u, &k2a, &k2b);   // k2 = second split of key(1)

    InitFar init;
    for (int b = 0; b < BB; ++b) {
        uint32_t o0, o1;
        threefry2x32_host(k2a, k2b, 0u, (uint32_t)b, &o0, &o1);
        init.v[b] = (int)((o0 ^ o1) & 0xFFFFu);
    }

    // 16-CTA clusters require the non-portable opt-in (idempotent, not captured)
    cudaFuncSetAttribute(fps_kernel, cudaFuncAttributeNonPortableClusterSizeAllowed, 1);

    fps_kernel<<<dim3(CHUNKS, BB), TFPS>>>(xyz, init);
    gather_kernel<<<dim3(BB, CC), 256>>>(xyz, feat, (float*)d_out);
}

// round 13
// speedup vs baseline: 1.2689x; 1.2689x over previous
#include <cuda_runtime.h>
#include <cstdint>

// Problem constants (from reference): B=8, N=65536, C=256, NPOINT=1024
#define BB        8
#define NN        65536
#define CC        256
#define NPOINTS   1024
#define CHUNKS    16                  // CTAs per batch == cluster size
#define TFPS      512                 // threads per FPS block
#define NWARP     (TFPS / 32)
#define PPB       (NN / CHUNKS)       // 4096 points per block
#define PPT       (PPB / TFPS)        // 8 points per thread

__device__ int g_inds[BB][NPOINTS];   // fully rewritten every run -> no init needed

struct InitFar { int v[BB]; };

// ---------------------------------------------------------------------------
// PTX helpers
// ---------------------------------------------------------------------------
__device__ __forceinline__ uint32_t smem_u32(const void* p) {
    uint32_t a;
    asm("{ .reg .u64 t; cvta.to.shared.u64 t, %1; cvt.u32.u64 %0, t; }" : "=r"(a) : "l"(p));
    return a;
}
__device__ __forceinline__ uint32_t my_ctarank() {
    uint32_t r; asm("mov.u32 %0, %%cluster_ctarank;" : "=r"(r)); return r;
}
__device__ __forceinline__ uint32_t mapa_u32(uint32_t local, uint32_t rank) {
    uint32_t r;
    asm("mapa.shared::cluster.u32 %0, %1, %2;" : "=r"(r) : "r"(local), "r"(rank));
    return r;
}
__device__ __forceinline__ void st_dsmem_u64(uint32_t addr, unsigned long long v) {
    asm volatile("st.relaxed.cluster.shared::cluster.u64 [%0], %1;" :: "r"(addr), "l"(v) : "memory");
}
__device__ __forceinline__ unsigned long long ld_smem_vol_u64(uint32_t addr) {
    unsigned long long v;
    asm volatile("ld.volatile.shared.u64 %0, [%1];" : "=l"(v) : "r"(addr) : "memory");
    return v;
}
__device__ __forceinline__ unsigned redux_max_u32(unsigned v) {
    unsigned r;
    asm volatile("redux.sync.max.u32 %0, %1, 0xffffffff;" : "=r"(r) : "r"(v));
    return r;
}
__device__ __forceinline__ void cluster_sync_all() {
    asm volatile("barrier.cluster.arrive.aligned;" ::: "memory");
    asm volatile("barrier.cluster.wait.aligned;"   ::: "memory");
}

// Two-stage argmax on (dist, key) via redux.sync.max — identical ordering to
// a u64 (dist<<32|key) max: dist primary, then larger key (keys derive from
// ~idx, so larger key == smaller index == jnp.argmax first-occurrence).
__device__ __forceinline__ void redux_argmax(unsigned d, unsigned k,
                                             unsigned* md, unsigned* wk) {
    const unsigned m = redux_max_u32(d);
    const unsigned c = (d == m) ? k : 0u;
    *md = m;
    *wk = redux_max_u32(c);
}

// ---------------------------------------------------------------------------
// FPS: one batch = one 16-CTA cluster. Coordinates of the winning point are
// FORWARDED through the cluster exchange, so the per-iteration centroid L2
// load disappears entirely (xyz is only read in the prologue).
//
// Per iteration (both __syncthreads kept — they PARK waiter warps, which the
// hi-wid-first arbiter otherwise lets starve warp 0):
//   compute (+coord tracking) -> warp redux argmax; lane0 stores (dist,key),
//   winner lane stores coords to s_red* (bar1-protected, no tags)
//   warp0: block redux argmax; winner lane stages coords via smem+syncwarp;
//   publish 3 INDIVIDUALLY phase-tagged words per peer slot (relaxed DSMEM):
//     w0 = dist(32) | phase<<16 | ienc16      (ienc16 = idx ^ 0xFFFF)
//     w1 = x(32)    | phase<<31 | y>>1
//     w2 = z(32)    | phase<<1  | y&1
//   poll own slot until all 3 tags match (per-lane spin, no ballot);
//   cluster redux argmax; winner lane writes s_bc = {far, x, y, z}
//   bar2 -> everyone reads far + centroid coords from s_bc (LDS, no LDG).
// Each word is self-tagged -> no fences/release needed; double buffer (it&1)
// + phase ((it>>1)&1) disambiguates (peers at most 1 iteration ahead).
// ---------------------------------------------------------------------------
__global__ __launch_bounds__(TFPS, 1) __cluster_dims__(CHUNKS, 1, 1)
void fps_kernel(const float* __restrict__ xyz, InitFar init) {
    const int b    = blockIdx.y;
    const int t    = threadIdx.x;
    const int lane = t & 31;
    const int warp = t >> 5;
    const uint32_t rank = my_ctarank();          // == blockIdx.x
    const int base = (int)rank * PPB;

    __shared__ unsigned long long s_slots[2][CHUNKS][4];  // 3 words + pad, 32B/slot
    __shared__ unsigned long long s_redA[NWARP];          // (dist<<32)|ienc32
    __shared__ unsigned s_redX[NWARP], s_redY[NWARP], s_redZ[NWARP];
    __shared__ unsigned s_stage[3];                       // warp0 coord staging
    __shared__ uint4 s_bc;                                // {far, x, y, z}

    // Tag words invalid for iterations 0/1 (they expect phase==0)
    if (t < 2 * CHUNKS) {
        unsigned long long* sl = s_slots[t >> 4][t & 15];
        sl[0] = 0x10000ull;        // w0 phase bit16 = 1
        sl[1] = 0x80000000ull;     // w1 phase bit31 = 1
        sl[2] = 0x2ull;            // w2 phase bit1  = 1
    }

    const float* __restrict__ xb = xyz + (size_t)b * NN * 3;

    float    px[PPT], py[PPT], pz[PPT], dist[PPT];
    unsigned ienc[PPT];
#pragma unroll
    for (int k = 0; k < PPT; ++k) {
        const int p = base + k * TFPS + t;
        const float* q = xb + 3 * (size_t)p;
        px[k] = q[0]; py[k] = q[1]; pz[k] = q[2];
        dist[k] = 1e10f;
        ienc[k] = ~(unsigned)p;
    }

    // DSMEM addresses (used by warp 0, lanes < CHUNKS)
    uint32_t st_addr[2], poll_addr[2];
    {
        const uint32_t l0 = smem_u32(&s_slots[0][rank][0]);
        const uint32_t l1 = smem_u32(&s_slots[1][rank][0]);
        const uint32_t peer = (lane < CHUNKS) ? (uint32_t)lane : 0u;
        st_addr[0] = mapa_u32(l0, peer);          // my words -> peer's slot[buf][rank]
        st_addr[1] = mapa_u32(l1, peer);
        poll_addr[0] = smem_u32(&s_slots[0][lane & 15][0]);  // my own slot[buf][lane]
        poll_addr[1] = smem_u32(&s_slots[1][lane & 15][0]);
    }

    __syncthreads();
    cluster_sync_all();   // all CTAs' slot tags initialized before any publish

    int far = init.v[b];
    // One-time centroid fetch; afterwards coordinates arrive via the exchange.
    float cx = __ldg(xb + 3 * (size_t)far + 0);
    float cy = __ldg(xb + 3 * (size_t)far + 1);
    float cz = __ldg(xb + 3 * (size_t)far + 2);

    for (int it = 0; it < NPOINTS; ++it) {
        const int buf = it & 1;
        const unsigned phase = (unsigned)((it >> 1) & 1);

        if (rank == 0 && t == 0) g_inds[b][it] = far;   // lax.scan pre-update index

        float    bd = -1.0f;
        unsigned bi = 0u;
        float    bx = 0.0f, by = 0.0f, bz = 0.0f;
#pragma unroll
        for (int k = 0; k < PPT; ++k) {
            // Match XLA (no FP contraction): sub, mul, (d0+d1)+d2, all RN
            const float dx = __fsub_rn(px[k], cx);
            const float dy = __fsub_rn(py[k], cy);
            const float dz = __fsub_rn(pz[k], cz);
            const float d  = __fadd_rn(__fadd_rn(__fmul_rn(dx, dx), __fmul_rn(dy, dy)),
                                       __fmul_rn(dz, dz));
            const float nd = fminf(dist[k], d);
            dist[k] = nd;
            if (nd > bd) { bd = nd; bi = ienc[k];          // strict > keeps smallest idx
                           bx = px[k]; by = py[k]; bz = pz[k]; }
        }

        // Warp argmax via 2x redux; lane0 stores (dist,key), winner stores coords
        const unsigned d0b = __float_as_uint(bd);
        unsigned m0, w0;
        redux_argmax(d0b, bi, &m0, &w0);
        if (lane == 0)
            s_redA[warp] = ((unsigned long long)m0 << 32) | (unsigned long long)w0;
        if (d0b == m0 && bi == w0) {                       // unique winner lane
            s_redX[warp] = __float_as_uint(bx);
            s_redY[warp] = __float_as_uint(by);
            s_redZ[warp] = __float_as_uint(bz);
        }
        __syncthreads();                                   // bar1 (parks warps 1..15)

        if (warp == 0) {
            // Block argmax over NWARP(16) entries
            const unsigned long long A = s_redA[lane & (NWARP - 1)];
            unsigned d2 = 0u, k2 = 0u;
            if (lane < NWARP) { d2 = (unsigned)(A >> 32); k2 = (unsigned)A; }
            unsigned m2, w2;
            redux_argmax(d2, k2, &m2, &w2);

            // Winner lane stages the block winner's coords for all lanes
            if (lane < NWARP && d2 == m2 && k2 == w2) {
                s_stage[0] = s_redX[lane];
                s_stage[1] = s_redY[lane];
                s_stage[2] = s_redZ[lane];
            }
            __syncwarp();
            const unsigned xw = s_stage[0];
            const unsigned yw = s_stage[1];
            const unsigned zw = s_stage[2];

            // Publish 3 self-tagged words to every CTA's slot[buf][rank]
            const unsigned ienc16 = w2 & 0xFFFFu;          // (~idx) low 16 bits
            const unsigned long long t0 =
                ((unsigned long long)m2 << 32) | (phase << 16) | ienc16;
            const unsigned long long t1 =
                ((unsigned long long)xw << 32) | ((unsigned long long)phase << 31)
                | (unsigned long long)(yw >> 1);
            const unsigned long long t2 =
                ((unsigned long long)zw << 32) | (phase << 1) | (yw & 1u);
            if (lane < CHUNKS) {
                st_dsmem_u64(st_addr[buf] + 0,  t0);
                st_dsmem_u64(st_addr[buf] + 8,  t1);
                st_dsmem_u64(st_addr[buf] + 16, t2);
            }

            // Poll own slot: per-lane spin until ALL 3 tags match, then syncwarp
            unsigned long long a0 = 0ull, a1 = 0ull, a2 = 0ull;
            if (lane < CHUNKS) {
                for (;;) {
                    a0 = ld_smem_vol_u64(poll_addr[buf] + 0);
                    a1 = ld_smem_vol_u64(poll_addr[buf] + 8);
                    a2 = ld_smem_vol_u64(poll_addr[buf] + 16);
                    const unsigned bad = ((((unsigned)(a0 >> 16)) ^ phase) & 1u)
                                       | ((((unsigned)(a1 >> 31)) ^ phase) & 1u)
                                       | ((((unsigned)(a2 >> 1))  ^ phase) & 1u);
                    if (!bad) break;
                }
            }
            __syncwarp();

            // Cluster argmax over the 16 slot values
            unsigned d3 = 0u, e3 = 0u;
            if (lane < CHUNKS) { d3 = (unsigned)(a0 >> 32); e3 = (unsigned)a0 & 0xFFFFu; }
            const unsigned m3 = redux_max_u32(d3);
            const unsigned c3 = (d3 == m3) ? e3 : 0u;
            const unsigned w3 = redux_max_u32(c3);

            // Winner lane decodes coords and broadcasts {far, x, y, z}
            if (lane < CHUNKS && d3 == m3 && e3 == w3) {
                const unsigned xr = (unsigned)(a1 >> 32);
                const unsigned y31 = (unsigned)a1 & 0x7FFFFFFFu;
                const unsigned yr = (y31 << 1) | ((unsigned)a2 & 1u);
                const unsigned zr = (unsigned)(a2 >> 32);
                s_bc = make_uint4(w3 ^ 0xFFFFu, xr, yr, zr);
            }
        }
        __syncthreads();                                   // bar2
        const uint4 bc = s_bc;
        far = (int)bc.x;
        cx = __uint_as_float(bc.y);
        cy = __uint_as_float(bc.z);
        cz = __uint_as_float(bc.w);
    }

    cluster_sync_all();   // no CTA exits while peers might still address its SMEM
}

// ---------------------------------------------------------------------------
// Gather outputs. d_out (float32) layout, concatenated in reference order:
//   [0)                    new_xyz      (B, NPOINT, 3)
//   [B*NPOINT*3)           new_features (B, C, NPOINT)
//   [.. + B*C*NPOINT)      sample_inds  (B, NPOINT)  (indices as float)
// ---------------------------------------------------------------------------
__global__ void gather_kernel(const float* __restrict__ xyz,
                              const float* __restrict__ feat,
                              float* __restrict__ out) {
    const int b = blockIdx.x;
    const int c = blockIdx.y;

    float* out_xyz  = out;
    float* out_feat = out + (size_t)BB * NPOINTS * 3;
    float* out_inds = out_feat + (size_t)BB * CC * NPOINTS;

    const float* frow = feat + ((size_t)b * CC + c) * NN;
    float*       orow = out_feat + ((size_t)b * CC + c) * NPOINTS;

    for (int j = threadIdx.x; j < NPOINTS; j += blockDim.x) {
        const int idx = g_inds[b][j];
        orow[j] = __ldg(frow + idx);
        if (c == 0) {
            out_inds[(size_t)b * NPOINTS + j] = (float)idx;
            const float* q = xyz + ((size_t)b * NN + idx) * 3;
            float* o = out_xyz + ((size_t)b * NPOINTS + j) * 3;
            o[0] = __ldg(q + 0); o[1] = __ldg(q + 1); o[2] = __ldg(q + 2);
        }
    }
}

// ---------------------------------------------------------------------------
// Host: reproduce jax.random.randint(jax.random.key(1), (8,), 0, 65536)
// under jax_threefry_partitionable=True (default since JAX 0.5.0).
//   k1, k2 = split(key(1));  lower = random_bits(k2, 32, (8,));  idx = lower & 0xFFFF
//   split:       newkey_j = threefry2x32((0,1), (0, j))
//   random_bits: bits[b]  = o0 ^ o1 of threefry2x32(k2, (0, b))
// ---------------------------------------------------------------------------
static void threefry2x32_host(uint32_t k0, uint32_t k1, uint32_t c0, uint32_t c1,
                              uint32_t* o0, uint32_t* o1) {
    const uint32_t ks[3] = { k0, k1, k0 ^ k1 ^ 0x1BD11BDAu };
    static const int rot0[4] = {13, 15, 26, 6};
    static const int rot1[4] = {17, 29, 16, 24};
    uint32_t x0 = c0 + ks[0];
    uint32_t x1 = c1 + ks[1];
    for (int i = 0; i < 5; ++i) {
        const int* rr = (i % 2 == 0) ? rot0 : rot1;
        for (int j = 0; j < 4; ++j) {
            x0 += x1;
            x1 = (x1 << rr[j]) | (x1 >> (32 - rr[j]));
            x1 ^= x0;
        }
        x0 += ks[(i + 1) % 3];
        x1 += ks[(i + 2) % 3] + (uint32_t)(i + 1);
    }
    *o0 = x0; *o1 = x1;
}

extern "C" void kernel_launch(void* const* d_in, const int* in_sizes, int n_in,
                              void* d_out, int out_size) {
    (void)in_sizes; (void)n_in; (void)out_size;
    const float* xyz  = (const float*)d_in[0];
    const float* feat = (const float*)d_in[1];

    uint32_t k2a, k2b;
    threefry2x32_host(0u, 1u, 0u, 1u, &k2a, &k2b);   // k2 = second split of key(1)

    InitFar init;
    for (int b = 0; b < BB; ++b) {
        uint32_t o0, o1;
        threefry2x32_host(k2a, k2b, 0u, (uint32_t)b, &o0, &o1);
        init.v[b] = (int)((o0 ^ o1) & 0xFFFFu);
    }

    // 16-CTA clusters require the non-portable opt-in (idempotent, not captured)
    cudaFuncSetAttribute(fps_kernel, cudaFuncAttributeNonPortableClusterSizeAllowed, 1);

    fps_kernel<<<dim3(CHUNKS, BB), TFPS>>>(xyz, init);
    gather_kernel<<<dim3(BB, CC), 256>>>(xyz, feat, (float*)d_out);
}

// round 14
// speedup vs baseline: 1.4966x; 1.1795x over previous
#include <cuda_runtime.h>
#include <cstdint>

// Problem constants (from reference): B=8, N=65536, C=256, NPOINT=1024
#define BB        8
#define NN        65536
#define CC        256
#define NPOINTS   1024
#define CHUNKS    16                  // CTAs per batch == cluster size
#define TFPS      512                 // threads per FPS block
#define NWARP     (TFPS / 32)
#define PPB       (NN / CHUNKS)       // 4096 points per block
#define PPT       (PPB / TFPS)        // 8 points per thread

// Dynamic smem layout: [0, PPB*3 floats) coord table, then control block.
#define SMEM_COORD_BYTES (PPB * 3 * 4)          // 49152
#define SMEM_CTRL_OFF    SMEM_COORD_BYTES
#define SMEM_TOTAL_BYTES (SMEM_CTRL_OFF + 2*CHUNKS*32 + NWARP*8 + 64)

__device__ int g_inds[BB][NPOINTS];   // fully rewritten every run -> no init needed

struct InitFar { int v[BB]; };

// ---------------------------------------------------------------------------
// PTX helpers
// ---------------------------------------------------------------------------
__device__ __forceinline__ uint32_t smem_u32(const void* p) {
    uint32_t a;
    asm("{ .reg .u64 t; cvta.to.shared.u64 t, %1; cvt.u32.u64 %0, t; }" : "=r"(a) : "l"(p));
    return a;
}
__device__ __forceinline__ uint32_t my_ctarank() {
    uint32_t r; asm("mov.u32 %0, %%cluster_ctarank;" : "=r"(r)); return r;
}
__device__ __forceinline__ uint32_t mapa_u32(uint32_t local, uint32_t rank) {
    uint32_t r;
    asm("mapa.shared::cluster.u32 %0, %1, %2;" : "=r"(r) : "r"(local), "r"(rank));
    return r;
}
__device__ __forceinline__ void st_dsmem_u64(uint32_t addr, unsigned long long v) {
    asm volatile("st.relaxed.cluster.shared::cluster.u64 [%0], %1;" :: "r"(addr), "l"(v) : "memory");
}
__device__ __forceinline__ unsigned long long ld_smem_vol_u64(uint32_t addr) {
    unsigned long long v;
    asm volatile("ld.volatile.shared.u64 %0, [%1];" : "=l"(v) : "r"(addr) : "memory");
    return v;
}
__device__ __forceinline__ unsigned redux_max_u32(unsigned v) {
    unsigned r;
    asm volatile("redux.sync.max.u32 %0, %1, 0xffffffff;" : "=r"(r) : "r"(v));
    return r;
}
__device__ __forceinline__ void cluster_sync_all() {
    asm volatile("barrier.cluster.arrive.aligned;" ::: "memory");
    asm volatile("barrier.cluster.wait.aligned;"   ::: "memory");
}

// Two-stage argmax on (dist, key) via redux.sync.max — identical ordering to
// a u64 (dist<<32|key) max: dist primary, then larger key (keys derive from
// ~idx, so larger key == smaller index == jnp.argmax first-occurrence).
__device__ __forceinline__ void redux_argmax(unsigned d, unsigned k,
                                             unsigned* md, unsigned* wk) {
    const unsigned m = redux_max_u32(d);
    const unsigned c = (d == m) ? k : 0u;
    *md = m;
    *wk = redux_max_u32(c);
}

// ---------------------------------------------------------------------------
// FPS: one batch = one 16-CTA cluster. The CTA's points are staged in a
// SHARED-MEMORY coordinate table in the prologue; the compute loop tracks only
// (dist, key) — no coordinate selects — and winner coordinates are fetched by
// an LDS broadcast (all lanes, same address) using local = ~key - base, since
// the block winner is by construction CTA-local. Coordinates then ride the
// cluster exchange (proven R13 protocol), so xyz GMEM is never read after the
// prologue.
//
// Per iteration (both __syncthreads kept — they PARK waiter warps, which the
// hi-wid-first arbiter otherwise lets starve warp 0):
//   compute -> warp redux argmax -> lane0 STS (dist,key) -> bar1
//   warp0: block redux argmax; all lanes LDS-broadcast winner coords;
//   publish 3 INDIVIDUALLY phase-tagged words per peer slot (relaxed DSMEM):
//     w0 = dist(32) | phase<<16 | ienc16      (ienc16 = idx ^ 0xFFFF)
//     w1 = x(32)    | phase<<31 | y>>1
//     w2 = z(32)    | phase<<1  | y&1
//   poll own slot until all 3 tags match; cluster redux argmax; winner lane
//   decodes coords -> s_bc -> bar2 -> everyone reads {far, cx, cy, cz}.
// Self-tagged words -> no fences; double buffer (it&1) + phase ((it>>1)&1)
// disambiguates (peers at most 1 iteration ahead by the data dependency).
// ---------------------------------------------------------------------------
__global__ __launch_bounds__(TFPS, 1) __cluster_dims__(CHUNKS, 1, 1)
void fps_kernel(const float* __restrict__ xyz, InitFar init) {
    extern __shared__ float smem_f[];
    float* s_coord = smem_f;                                  // [PPB*3]
    char*  s_ctrl  = (char*)smem_f + SMEM_CTRL_OFF;
    unsigned long long (*s_slots)[CHUNKS][4] =
        (unsigned long long (*)[CHUNKS][4])(s_ctrl);          // [2][CHUNKS][4]
    unsigned long long* s_redA =
        (unsigned long long*)(s_ctrl + 2 * CHUNKS * 32);      // [NWARP]
    uint4* s_bc = (uint4*)(s_ctrl + 2 * CHUNKS * 32 + NWARP * 8);

    const int b    = blockIdx.y;
    const int t    = threadIdx.x;
    const int lane = t & 31;
    const int warp = t >> 5;
    const uint32_t rank = my_ctarank();          // == blockIdx.x
    const int base = (int)rank * PPB;

    // Tag words invalid for iterations 0/1 (they expect phase==0)
    if (t < 2 * CHUNKS) {
        unsigned long long* sl = s_slots[t >> 4][t & 15];
        sl[0] = 0x10000ull;        // w0 phase bit16 = 1
        sl[1] = 0x80000000ull;     // w1 phase bit31 = 1
        sl[2] = 0x2ull;            // w2 phase bit1  = 1
    }

    const float* __restrict__ xb = xyz + (size_t)b * NN * 3;

    float    px[PPT], py[PPT], pz[PPT], dist[PPT];
    unsigned ienc[PPT];
#pragma unroll
    for (int k = 0; k < PPT; ++k) {
        const int p = base + k * TFPS + t;
        const float* q = xb + 3 * (size_t)p;
        const float x = q[0], y = q[1], z = q[2];
        px[k] = x; py[k] = y; pz[k] = z;
        dist[k] = 1e10f;
        ienc[k] = ~(unsigned)p;
        // Stage into the smem coordinate table (local index = p - base)
        const int loc = k * TFPS + t;
        s_coord[loc * 3 + 0] = x;
        s_coord[loc * 3 + 1] = y;
        s_coord[loc * 3 + 2] = z;
    }

    // DSMEM addresses (used by warp 0, lanes < CHUNKS)
    uint32_t st_addr[2], poll_addr[2];
    {
        const uint32_t l0 = smem_u32(&s_slots[0][rank][0]);
        const uint32_t l1 = smem_u32(&s_slots[1][rank][0]);
        const uint32_t peer = (lane < CHUNKS) ? (uint32_t)lane : 0u;
        st_addr[0] = mapa_u32(l0, peer);          // my words -> peer's slot[buf][rank]
        st_addr[1] = mapa_u32(l1, peer);
        poll_addr[0] = smem_u32(&s_slots[0][lane & 15][0]);  // my own slot[buf][lane]
        poll_addr[1] = smem_u32(&s_slots[1][lane & 15][0]);
    }

    __syncthreads();      // coord table + slot tags ready (this CTA)
    cluster_sync_all();   // all CTAs' slot tags initialized before any publish

    int far = init.v[b];
    // One-time centroid fetch; afterwards coordinates arrive via the exchange.
    float cx = __ldg(xb + 3 * (size_t)far + 0);
    float cy = __ldg(xb + 3 * (size_t)far + 1);
    float cz = __ldg(xb + 3 * (size_t)far + 2);

    for (int it = 0; it < NPOINTS; ++it) {
        const int buf = it & 1;
        const unsigned phase = (unsigned)((it >> 1) & 1);

        if (rank == 0 && t == 0) g_inds[b][it] = far;   // lax.scan pre-update index

        float    bd = -1.0f;
        unsigned bi = 0u;
#pragma unroll
        for (int k = 0; k < PPT; ++k) {
            // Match XLA (no FP contraction): sub, mul, (d0+d1)+d2, all RN
            const float dx = __fsub_rn(px[k], cx);
            const float dy = __fsub_rn(py[k], cy);
            const float dz = __fsub_rn(pz[k], cz);
            const float d  = __fadd_rn(__fadd_rn(__fmul_rn(dx, dx), __fmul_rn(dy, dy)),
                                       __fmul_rn(dz, dz));
            const float nd = fminf(dist[k], d);
            dist[k] = nd;
            if (nd > bd) { bd = nd; bi = ienc[k]; }     // strict > keeps smallest idx
        }

        // Warp argmax via 2x redux; lane0 stores (dist,key)
        unsigned m0, w0;
        redux_argmax(__float_as_uint(bd), bi, &m0, &w0);
        if (lane == 0)
            s_redA[warp] = ((unsigned long long)m0 << 32) | (unsigned long long)w0;
        __syncthreads();                                   // bar1 (parks warps 1..15)

        if (warp == 0) {
            // Block argmax over NWARP(16) entries
            const unsigned long long A = s_redA[lane & (NWARP - 1)];
            unsigned d2 = 0u, k2 = 0u;
            if (lane < NWARP) { d2 = (unsigned)(A >> 32); k2 = (unsigned)A; }
            unsigned m2, w2;
            redux_argmax(d2, k2, &m2, &w2);

            // Winner coords: block winner is CTA-local; all lanes read the
            // same smem address -> LDS broadcast, no staging, no syncwarp.
            const int loc = (int)((~w2) & 0xFFFFu) - base;
            const unsigned xw = __float_as_uint(s_coord[loc * 3 + 0]);
            const unsigned yw = __float_as_uint(s_coord[loc * 3 + 1]);
            const unsigned zw = __float_as_uint(s_coord[loc * 3 + 2]);

            // Publish 3 self-tagged words to every CTA's slot[buf][rank]
            const unsigned ienc16 = w2 & 0xFFFFu;          // (~idx) low 16 bits
            const unsigned long long t0 =
                ((unsigned long long)m2 << 32) | (phase << 16) | ienc16;
            const unsigned long long t1 =
                ((unsigned long long)xw << 32) | ((unsigned long long)phase << 31)
                | (unsigned long long)(yw >> 1);
            const unsigned long long t2 =
                ((unsigned long long)zw << 32) | (phase << 1) | (yw & 1u);
            if (lane < CHUNKS) {
                st_dsmem_u64(st_addr[buf] + 0,  t0);
                st_dsmem_u64(st_addr[buf] + 8,  t1);
                st_dsmem_u64(st_addr[buf] + 16, t2);
            }

            // Poll own slot: per-lane spin until ALL 3 tags match, then syncwarp
            unsigned long long a0 = 0ull, a1 = 0ull, a2 = 0ull;
            if (lane < CHUNKS) {
                for (;;) {
                    a0 = ld_smem_vol_u64(poll_addr[buf] + 0);
                    a1 = ld_smem_vol_u64(poll_addr[buf] + 8);
                    a2 = ld_smem_vol_u64(poll_addr[buf] + 16);
                    const unsigned bad = ((((unsigned)(a0 >> 16)) ^ phase) & 1u)
                                       | ((((unsigned)(a1 >> 31)) ^ phase) & 1u)
                                       | ((((unsigned)(a2 >> 1))  ^ phase) & 1u);
                    if (!bad) break;
                }
            }
            __syncwarp();

            // Cluster argmax over the 16 slot values
            unsigned d3 = 0u, e3 = 0u;
            if (lane < CHUNKS) { d3 = (unsigned)(a0 >> 32); e3 = (unsigned)a0 & 0xFFFFu; }
            const unsigned m3 = redux_max_u32(d3);
            const unsigned c3 = (d3 == m3) ? e3 : 0u;
            const unsigned w3 = redux_max_u32(c3);

            // Winner lane decodes coords and broadcasts {far, x, y, z}
            if (lane < CHUNKS && d3 == m3 && e3 == w3) {
                const unsigned xr = (unsigned)(a1 >> 32);
                const unsigned y31 = (unsigned)a1 & 0x7FFFFFFFu;
                const unsigned yr = (y31 << 1) | ((unsigned)a2 & 1u);
                const unsigned zr = (unsigned)(a2 >> 32);
                *s_bc = make_uint4(w3 ^ 0xFFFFu, xr, yr, zr);
            }
        }
        __syncthreads();                                   // bar2
        const uint4 bc = *s_bc;
        far = (int)bc.x;
        cx = __uint_as_float(bc.y);
        cy = __uint_as_float(bc.z);
        cz = __uint_as_float(bc.w);
    }

    cluster_sync_all();   // no CTA exits while peers might still address its SMEM
}

// ---------------------------------------------------------------------------
// Gather outputs. d_out (float32) layout, concatenated in reference order:
//   [0)                    new_xyz      (B, NPOINT, 3)
//   [B*NPOINT*3)           new_features (B, C, NPOINT)
//   [.. + B*C*NPOINT)      sample_inds  (B, NPOINT)  (indices as float)
// ---------------------------------------------------------------------------
__global__ void gather_kernel(const float* __restrict__ xyz,
                              const float* __restrict__ feat,
                              float* __restrict__ out) {
    const int b = blockIdx.x;
    const int c = blockIdx.y;

    float* out_xyz  = out;
    float* out_feat = out + (size_t)BB * NPOINTS * 3;
    float* out_inds = out_feat + (size_t)BB * CC * NPOINTS;

    const float* frow = feat + ((size_t)b * CC + c) * NN;
    float*       orow = out_feat + ((size_t)b * CC + c) * NPOINTS;

    for (int j = threadIdx.x; j < NPOINTS; j += blockDim.x) {
        const int idx = g_inds[b][j];
        orow[j] = __ldg(frow + idx);
        if (c == 0) {
            out_inds[(size_t)b * NPOINTS + j] = (float)idx;
            const float* q = xyz + ((size_t)b * NN + idx) * 3;
            float* o = out_xyz + ((size_t)b * NPOINTS + j) * 3;
            o[0] = __ldg(q + 0); o[1] = __ldg(q + 1); o[2] = __ldg(q + 2);
        }
    }
}

// ---------------------------------------------------------------------------
// Host: reproduce jax.random.randint(jax.random.key(1), (8,), 0, 65536)
// under jax_threefry_partitionable=True (default since JAX 0.5.0).
//   k1, k2 = split(key(1));  lower = random_bits(k2, 32, (8,));  idx = lower & 0xFFFF
//   split:       newkey_j = threefry2x32((0,1), (0, j))
//   random_bits: bits[b]  = o0 ^ o1 of threefry2x32(k2, (0, b))
// ---------------------------------------------------------------------------
static void threefry2x32_host(uint32_t k0, uint32_t k1, uint32_t c0, uint32_t c1,
                              uint32_t* o0, uint32_t* o1) {
    const uint32_t ks[3] = { k0, k1, k0 ^ k1 ^ 0x1BD11BDAu };
    static const int rot0[4] = {13, 15, 26, 6};
    static const int rot1[4] = {17, 29, 16, 24};
    uint32_t x0 = c0 + ks[0];
    uint32_t x1 = c1 + ks[1];
    for (int i = 0; i < 5; ++i) {
        const int* rr = (i % 2 == 0) ? rot0 : rot1;
        for (int j = 0; j < 4; ++j) {
            x0 += x1;
            x1 = (x1 << rr[j]) | (x1 >> (32 - rr[j]));
            x1 ^= x0;
        }
        x0 += ks[(i + 1) % 3];
        x1 += ks[(i + 2) % 3] + (uint32_t)(i + 1);
    }
    *o0 = x0; *o1 = x1;
}

extern "C" void kernel_launch(void* const* d_in, const int* in_sizes, int n_in,
                              void* d_out, int out_size) {
    (void)in_sizes; (void)n_in; (void)out_size;
    const float* xyz  = (const float*)d_in[0];
    const float* feat = (const float*)d_in[1];

    uint32_t k2a, k2b;
    threefry2x32_host(0u, 1u, 0u, 1u, &k2a, &k2b);   // k2 = second split of key(1)

    InitFar init;
    for (int b = 0; b < BB; ++b) {
        uint32_t o0, o1;
        threefry2x32_host(k2a, k2b, 0u, (uint32_t)b, &o0, &o1);
        init.v[b] = (int)((o0 ^ o1) & 0xFFFFu);
    }

    // Idempotent attributes (host-side, not captured): non-portable 16-CTA
    // cluster + dynamic smem above the 48KB static limit.
    cudaFuncSetAttribute(fps_kernel, cudaFuncAttributeNonPortableClusterSizeAllowed, 1);
    cudaFuncSetAttribute(fps_kernel, cudaFuncAttributeMaxDynamicSharedMemorySize,
                         SMEM_TOTAL_BYTES);

    fps_kernel<<<dim3(CHUNKS, BB), TFPS, SMEM_TOTAL_BYTES>>>(xyz, init);
    gather_kernel<<<dim3(BB, CC), 256>>>(xyz, feat, (float*)d_out);
}